// round 16
// baseline (speedup 1.0000x reference)
#include <cuda_runtime.h>
#include <cuda_fp16.h>
#include <cstdint>

#define NTH   256
#define MR    128
#define BTOT  131072
#define GRID  (BTOT / MR)
#define WROWS 2048

// SMEM byte offsets
#define OFF_A    0        // 65536: A operand fp16 [128][256], 512B row stride, XOR swizzle
#define OFF_B    65536    // 131072: FULL B fp16 [256][256], 512B row stride, XOR swizzle
                          //   ps overlay (64 x 185 fp32 = 47360) during spline
#define OFF_SMIN 196608   // 33280: input/output tile fp32 [128][65]
#define SMEM_BYTES 229888

__device__ __align__(16) __half g_w[(size_t)WROWS * 256u];   // fp16 weight plane
__device__ float g_h[(size_t)BTOT * 256u];                   // residual-h scratch (fp32)

static __device__ __forceinline__ uint32_t smem_u32(const void* p) {
    uint32_t a;
    asm("{ .reg .u64 t; cvta.to.shared.u64 t, %1; cvt.u32.u64 %0, t; }" : "=r"(a) : "l"(p));
    return a;
}
static __device__ __forceinline__ void ldmx4(uint32_t* r, uint32_t a) {
    asm volatile("ldmatrix.sync.aligned.m8n8.x4.shared.b16 {%0,%1,%2,%3}, [%4];"
                 : "=r"(r[0]), "=r"(r[1]), "=r"(r[2]), "=r"(r[3]) : "r"(a));
}
static __device__ __forceinline__ void mma_f16(float* c, const uint32_t* a, const uint32_t* b) {
    asm volatile("mma.sync.aligned.m16n8k16.row.col.f32.f16.f16.f32 "
                 "{%0,%1,%2,%3}, {%4,%5,%6,%7}, {%8,%9}, {%0,%1,%2,%3};"
                 : "+f"(c[0]), "+f"(c[1]), "+f"(c[2]), "+f"(c[3])
                 : "r"(a[0]), "r"(a[1]), "r"(a[2]), "r"(a[3]), "r"(b[0]), "r"(b[1]));
}
static __device__ __forceinline__ uint32_t pack_h2(float x0, float x1) {
    __half2 h2 = __float22half2_rn(make_float2(x0, x1));
    return *(uint32_t*)&h2;
}

// ---------------- weight convert kernel (fp32 -> single fp16 plane) ----------------
// rows: 0-255 w_in | 256-511 w0a | 512-767 w1a | 768-1023 w0b | 1024-1279 w1b
//       1280-2015 w_out (tight) | 2016-2047 zero pad
__global__ void split_weights_kernel(
    const float* __restrict__ w_in, const float* __restrict__ w0a,
    const float* __restrict__ w1a,  const float* __restrict__ w0b,
    const float* __restrict__ w1b,  const float* __restrict__ w_out)
{
    int row = blockIdx.x;
    int c = threadIdx.x;
    float v = 0.f;
    if (row < 256)       { if (c < 32) v = w_in[row * 32 + c]; }
    else if (row < 512)  v = w0a[(row - 256) * 256 + c];
    else if (row < 768)  v = w1a[(row - 512) * 256 + c];
    else if (row < 1024) v = w0b[(row - 768) * 256 + c];
    else if (row < 1280) v = w1b[(row - 1024) * 256 + c];
    else if (row < 2016) v = w_out[(row - 1280) * 256 + c];
    g_w[(size_t)row * 256 + c] = __float2half(v);
}

// ---------------- one K=16 chunk, both M-tiles, N=256: 8 ldm + 32 mma / warp ----------------
static __device__ __forceinline__ void compute_pair(
    uint32_t Aop, uint32_t Bop, float* acc0, float* acc1, int wm, int wn, int k0, int lane)
{
    uint32_t ah0[2][4], ah1[2][4];
    #pragma unroll
    for (int mt = 0; mt < 2; mt++) {
        int r0 = 32 * wm + 16 * mt + (lane & 15);
        int c = (k0 >> 3) + (lane >> 4);
        uint32_t ad0 = Aop + r0 * 512 + ((uint32_t)(c ^ (r0 & 7)) << 4);
        ldmx4(ah0[mt], ad0);
        int r1 = r0 + 64;
        uint32_t ad1 = Aop + r1 * 512 + ((uint32_t)(c ^ (r1 & 7)) << 4);
        ldmx4(ah1[mt], ad1);
    }
    uint32_t bh[4][4];
    #pragma unroll
    for (int g = 0; g < 4; g++) {
        int r = 64 * wn + 16 * g + (lane & 15);
        int c = (k0 >> 3) + (lane >> 4);
        uint32_t bd = Bop + r * 512 + ((uint32_t)(c ^ (r & 7)) << 4);
        ldmx4(bh[g], bd);
    }
    #pragma unroll
    for (int mt = 0; mt < 2; mt++)
        #pragma unroll
        for (int nt = 0; nt < 8; nt++) {
            int g = nt >> 1, o = nt & 1;
            uint32_t b0[2] = { bh[g][o], bh[g][o + 2] };
            mma_f16(acc0 + (mt * 8 + nt) * 4, ah0[mt], b0);
            mma_f16(acc1 + (mt * 8 + nt) * 4, ah1[mt], b0);
        }
}

// ---------------- same, N=192 (w_out): 7 ldm + 24 mma / warp ----------------
static __device__ __forceinline__ void compute_pair192(
    uint32_t Aop, uint32_t Bop, float* acc0, float* acc1, int wm, int wn, int k0, int lane)
{
    uint32_t ah0[2][4], ah1[2][4];
    #pragma unroll
    for (int mt = 0; mt < 2; mt++) {
        int r0 = 32 * wm + 16 * mt + (lane & 15);
        int c = (k0 >> 3) + (lane >> 4);
        uint32_t ad0 = Aop + r0 * 512 + ((uint32_t)(c ^ (r0 & 7)) << 4);
        ldmx4(ah0[mt], ad0);
        int r1 = r0 + 64;
        uint32_t ad1 = Aop + r1 * 512 + ((uint32_t)(c ^ (r1 & 7)) << 4);
        ldmx4(ah1[mt], ad1);
    }
    uint32_t bh[3][4];
    #pragma unroll
    for (int g = 0; g < 3; g++) {
        int r = 48 * wn + 16 * g + (lane & 15);
        int c = (k0 >> 3) + (lane >> 4);
        uint32_t bd = Bop + r * 512 + ((uint32_t)(c ^ (r & 7)) << 4);
        ldmx4(bh[g], bd);
    }
    #pragma unroll
    for (int mt = 0; mt < 2; mt++)
        #pragma unroll
        for (int nt = 0; nt < 6; nt++) {
            int g = nt >> 1, o = nt & 1;
            uint32_t b0[2] = { bh[g][o], bh[g][o + 2] };
            mma_f16(acc0 + (mt * 8 + nt) * 4, ah0[mt], b0);
            mma_f16(acc1 + (mt * 8 + nt) * 4, ah1[mt], b0);
        }
}

// ---------------- full-B-resident GEMM: stage once, then barrier-free unrolled mainloop ----------------
template <int N256, int KCH>
static __device__ __forceinline__ void run_gemm(
    uint32_t smb, uint32_t Aop, int rowbase,
    float* acc0, float* acc1, int wm, int wn, int lane, int tid)
{
    const int rows = N256 ? 256 : 192;
    #pragma unroll
    for (int q = 0; q < 64; q++) { acc0[q] = 0.f; acc1[q] = 0.f; }
    const uint32_t Bop = smb + OFF_B;
    // stage entire B (rows x KCH*16 k) with XOR swizzle, 16B pieces
    const int pieces = KCH * 2;            // 16B pieces per row
    const int total = rows * pieces;
    #pragma unroll 4
    for (int o = tid; o < total; o += NTH) {
        int row = o / pieces, p = o - row * pieces;
        const __half* src = g_w + (size_t)(rowbase + row) * 256 + p * 8;
        uint32_t dst = Bop + row * 512 + ((uint32_t)(p ^ (row & 7)) << 4);
        asm volatile("cp.async.cg.shared.global [%0], [%1], 16;" :: "r"(dst), "l"(src));
    }
    asm volatile("cp.async.commit_group;");
    asm volatile("cp.async.wait_group 0;");
    __syncthreads();
    // barrier-free mainloop; unroll 4 makes k0 affine -> addresses constant-fold
    #pragma unroll 4
    for (int t = 0; t < KCH; t++) {
        if (N256) compute_pair(Aop, Bop, acc0, acc1, wm, wn, 16 * t, lane);
        else      compute_pair192(Aop, Bop, acc0, acc1, wm, wn, 16 * t, lane);
    }
    __syncthreads();   // all reads of A/B done before epilogue overwrites A / ps overlays B
}

// per-tile epilogue. MODE 0: h=C+b (store h), relu->A | 1: relu(C+b)->A
// MODE 2: h=h_old+C+b (store h), relu->A | 3: h=h_old+C+b, raw->A (no h store)
template <int MODE>
static __device__ __forceinline__ void epi_tile(
    char* sm, const float* acc, const float* __restrict__ bias,
    int tile, int row0, int wm, int wn, int lane)
{
    #pragma unroll
    for (int mt = 0; mt < 2; mt++)
        #pragma unroll
        for (int nt = 0; nt < 8; nt++) {
            const float* a = acc + (mt * 8 + nt) * 4;
            int c0 = 64 * wn + 8 * nt + 2 * (lane & 3);
            float bb0 = __ldg(bias + c0);
            float bb1 = __ldg(bias + c0 + 1);
            #pragma unroll
            for (int hf = 0; hf < 2; hf++) {
                int rl = 64 * tile + 32 * wm + 16 * mt + (lane >> 2) + 8 * hf;
                float v0 = a[2 * hf] + bb0, v1 = a[2 * hf + 1] + bb1;
                float* hp = g_h + (size_t)(row0 + rl) * 256 + c0;
                if (MODE == 2 || MODE == 3) {
                    float2 ho = *(float2*)hp;
                    v0 += ho.x; v1 += ho.y;
                }
                if (MODE == 0 || MODE == 2) *(float2*)hp = make_float2(v0, v1);
                float w0 = v0, w1 = v1;
                if (MODE != 3) { w0 = fmaxf(w0, 0.f); w1 = fmaxf(w1, 0.f); }
                int u = 8 * wn + nt;
                uint32_t off = OFF_A + rl * 512
                             + ((uint32_t)(u ^ (rl & 7)) << 4) + 4 * (lane & 3);
                *(uint32_t*)(sm + off) = pack_h2(w0, w1);
            }
        }
}

// w_out epilogue for ONE tile: C -> ps fp32 [64][185] (overlaid on B region)
static __device__ __forceinline__ void epilogue_ps(
    char* sm, const float* acc, int wm, int wn, int lane)
{
    float* ps = (float*)(sm + OFF_B);
    #pragma unroll
    for (int mt = 0; mt < 2; mt++)
        #pragma unroll
        for (int nt = 0; nt < 6; nt++) {
            const float* a = acc + (mt * 8 + nt) * 4;
            int c0 = 48 * wn + 8 * nt + 2 * (lane & 3);
            #pragma unroll
            for (int hf = 0; hf < 2; hf++) {
                int r = 32 * wm + 16 * mt + (lane >> 2) + 8 * hf;
                if (c0 < 184)     ps[r * 185 + c0]     = a[2 * hf];
                if (c0 + 1 < 184) ps[r * 185 + c0 + 1] = a[2 * hf + 1];
            }
        }
}

// spline for 2 dims of one row of one tile (ps holds this tile's 64 rows)
static __device__ __forceinline__ void spline_block(
    char* sm, float* smin, const float* __restrict__ b_out,
    int p, int tile, int tid, float* lad)
{
    float* ps = (float*)(sm + OFF_B);
    int r = tid >> 2, s = tid & 3;
    int rs = 64 * tile + r;
    #pragma unroll 1
    for (int dd = 0; dd < 2; dd++) {
        int dl = s + 4 * dd;
        int gd = 8 * p + dl;
        const float* qp = ps + r * 185 + dl * 23;
        float pp[23];
        #pragma unroll
        for (int j = 0; j < 23; j++) pp[j] = qp[j] + __ldg(b_out + gd * 23 + j);
        float knw[9], knh[9], dv[9];
        {
            float e[8], mx = -1e30f;
            #pragma unroll
            for (int j = 0; j < 8; j++) { e[j] = pp[j] * 0.0625f; mx = fmaxf(mx, e[j]); }
            float se = 0.f;
            #pragma unroll
            for (int j = 0; j < 8; j++) { e[j] = expf(e[j] - mx); se += e[j]; }
            float inv = 1.f / se, cum = 0.f;
            knw[0] = -3.f;
            #pragma unroll
            for (int j = 0; j < 8; j++) { cum += 0.001f + 0.992f * e[j] * inv; knw[j + 1] = 6.f * cum - 3.f; }
            knw[8] = 3.f;
        }
        {
            float e[8], mx = -1e30f;
            #pragma unroll
            for (int j = 0; j < 8; j++) { e[j] = pp[8 + j] * 0.0625f; mx = fmaxf(mx, e[j]); }
            float se = 0.f;
            #pragma unroll
            for (int j = 0; j < 8; j++) { e[j] = expf(e[j] - mx); se += e[j]; }
            float inv = 1.f / se, cum = 0.f;
            knh[0] = -3.f;
            #pragma unroll
            for (int j = 0; j < 8; j++) { cum += 0.001f + 0.992f * e[j] * inv; knh[j + 1] = 6.f * cum - 3.f; }
            knh[8] = 3.f;
        }
        dv[0] = 1.f; dv[8] = 1.f;
        #pragma unroll
        for (int j = 1; j < 8; j++) {
            float t = pp[15 + j];
            dv[j] = 0.001f + fmaxf(t, 0.f) + log1pf(expf(-fabsf(t)));
        }
        float x  = smin[rs * 65 + 2 * gd];
        float xc = fminf(fmaxf(x, -3.f), 3.f);
        int idx = -1;
        #pragma unroll
        for (int j = 0; j < 9; j++) idx += (xc >= knw[j]) ? 1 : 0;
        idx = min(max(idx, 0), 7);
        float kw0 = knw[idx], kw1 = knw[idx + 1];
        float kh0 = knh[idx], kh1 = knh[idx + 1];
        float wdt = kw1 - kw0, hgt = kh1 - kh0;
        float delta = hgt / wdt;
        float d0v = dv[idx], d1v = dv[idx + 1];
        float th  = (xc - kw0) / wdt;
        float tom = th * (1.f - th);
        float num = hgt * (delta * th * th + d0v * tom);
        float den = delta + (d0v + d1v - 2.f * delta) * tom;
        float y   = kh0 + num / den;
        float omt = 1.f - th;
        float dnum = delta * delta * (d1v * th * th + 2.f * delta * tom + d0v * omt * omt);
        float ld   = logf(dnum) - 2.f * logf(den);
        bool inside = (x >= -3.f) && (x <= 3.f);
        if (!inside) { y = x; ld = 0.f; }
        smin[rs * 65 + 2 * gd] = y;
        *lad += ld;
    }
}

__global__ void __launch_bounds__(NTH, 1)
coupling_mma_kernel(const float* __restrict__ inp,
                    const float* __restrict__ b_in,
                    const float* __restrict__ b0a, const float* __restrict__ b1a,
                    const float* __restrict__ b0b, const float* __restrict__ b1b,
                    const float* __restrict__ b_out,
                    float* __restrict__ out)
{
    extern __shared__ char sm[];
    const int tid = threadIdx.x, lane = tid & 31, wrp = tid >> 5;
    const int wm = wrp >> 2, wn = wrp & 3;        // 2 x 4 warp grid per tile
    const int row0 = blockIdx.x * MR;
    const uint32_t smb = smem_u32(sm);
    float* smin = (float*)(sm + OFF_SMIN);

    // ---- load input tile 128 x 64 (stride 65) ----
    #pragma unroll
    for (int i = 0; i < 32; i++) {
        int idx = tid + NTH * i;
        int r = idx >> 6, c = idx & 63;
        smin[r * 65 + c] = inp[(size_t)(row0 + r) * 64 + c];
    }
    __syncthreads();

    // ---- ident (odd cols) -> A as fp16, k = 0..31 (2 threads/row) ----
    {
        int r = tid >> 1, s = tid & 1;
        #pragma unroll
        for (int kk = 0; kk < 16; kk += 2) {
            int k = 16 * s + kk;
            float v0 = smin[r * 65 + 2 * k + 1];
            float v1 = smin[r * 65 + 2 * k + 3];
            int u = k >> 3;
            uint32_t off = OFF_A + r * 512
                         + ((uint32_t)(u ^ (r & 7)) << 4) + (k & 7) * 2;
            *(uint32_t*)(sm + off) = pack_h2(v0, v1);
        }
    }
    // visibility via the __syncthreads inside run_gemm before first compute

    float acc0[64], acc1[64];
    const uint32_t Aop = smb + OFF_A;

    run_gemm<1, 2>(smb, Aop, 0, acc0, acc1, wm, wn, lane, tid);     // w_in (K=32)
    epi_tile<0>(sm, acc0, b_in, 0, row0, wm, wn, lane);
    epi_tile<0>(sm, acc1, b_in, 1, row0, wm, wn, lane);
    run_gemm<1, 16>(smb, Aop, 256, acc0, acc1, wm, wn, lane, tid);  // w0a
    epi_tile<1>(sm, acc0, b0a, 0, row0, wm, wn, lane);
    epi_tile<1>(sm, acc1, b0a, 1, row0, wm, wn, lane);
    run_gemm<1, 16>(smb, Aop, 512, acc0, acc1, wm, wn, lane, tid);  // w1a
    epi_tile<2>(sm, acc0, b1a, 0, row0, wm, wn, lane);
    epi_tile<2>(sm, acc1, b1a, 1, row0, wm, wn, lane);
    run_gemm<1, 16>(smb, Aop, 768, acc0, acc1, wm, wn, lane, tid);  // w0b
    epi_tile<1>(sm, acc0, b0b, 0, row0, wm, wn, lane);
    epi_tile<1>(sm, acc1, b0b, 1, row0, wm, wn, lane);
    run_gemm<1, 16>(smb, Aop, 1024, acc0, acc1, wm, wn, lane, tid); // w1b -> raw h
    epi_tile<3>(sm, acc0, b1b, 0, row0, wm, wn, lane);
    epi_tile<3>(sm, acc1, b1b, 1, row0, wm, wn, lane);

    // ---- w_out: 4 passes x 184 tight cols (8 dims x 23), N=192 GEMM, per-tile spline ----
    float lad0 = 0.f, lad1 = 0.f;
    #pragma unroll 1
    for (int p = 0; p < 4; p++) {
        run_gemm<0, 16>(smb, Aop, 1280 + 184 * p, acc0, acc1, wm, wn, lane, tid);
        epilogue_ps(sm, acc0, wm, wn, lane);
        __syncthreads();
        spline_block(sm, smin, b_out, p, 0, tid, &lad0);
        __syncthreads();
        epilogue_ps(sm, acc1, wm, wn, lane);
        __syncthreads();
        spline_block(sm, smin, b_out, p, 1, tid, &lad1);
        __syncthreads();    // ps consumed before next pass stages into B region
    }

    lad0 += __shfl_xor_sync(0xffffffffu, lad0, 1);
    lad0 += __shfl_xor_sync(0xffffffffu, lad0, 2);
    lad1 += __shfl_xor_sync(0xffffffffu, lad1, 1);
    lad1 += __shfl_xor_sync(0xffffffffu, lad1, 2);

    __syncthreads();
    #pragma unroll
    for (int i = 0; i < 32; i++) {
        int idx = tid + NTH * i;
        int r = idx >> 6, c = idx & 63;
        out[(size_t)(row0 + r) * 64 + c] = smin[r * 65 + c];
    }
    if ((tid & 3) == 0) {
        out[(size_t)BTOT * 64 + row0 + (tid >> 2)]      = lad0;
        out[(size_t)BTOT * 64 + row0 + 64 + (tid >> 2)] = lad1;
    }
}

extern "C" void kernel_launch(void* const* d_in, const int* in_sizes, int n_in,
                              void* d_out, int out_size)
{
    cudaFuncSetAttribute(coupling_mma_kernel,
                         cudaFuncAttributeMaxDynamicSharedMemorySize, SMEM_BYTES);
    const float* inp   = (const float*)d_in[0];
    const float* w_in  = (const float*)d_in[1];
    const float* b_in  = (const float*)d_in[2];
    const float* w0a   = (const float*)d_in[3];
    const float* b0a   = (const float*)d_in[4];
    const float* w1a   = (const float*)d_in[5];
    const float* b1a   = (const float*)d_in[6];
    const float* w0b   = (const float*)d_in[7];
    const float* b0b   = (const float*)d_in[8];
    const float* w1b   = (const float*)d_in[9];
    const float* b1b   = (const float*)d_in[10];
    const float* w_out = (const float*)d_in[11];
    const float* b_out = (const float*)d_in[12];
    float* out = (float*)d_out;

    split_weights_kernel<<<WROWS, 256>>>(w_in, w0a, w1a, w0b, w1b, w_out);
    coupling_mma_kernel<<<GRID, NTH, SMEM_BYTES>>>(
        inp, b_in, b0a, b1a, b0b, b1b, b_out, out);
}

// round 17
// speedup vs baseline: 1.0703x; 1.0703x over previous
#include <cuda_runtime.h>
#include <cuda_fp16.h>
#include <cstdint>

#define NTH   512
#define MR    128
#define BTOT  131072
#define GRID  (BTOT / MR)
#define WROWS 2048

// SMEM byte offsets
#define OFF_A    0        // 65536: A operand fp16 [128][256], 512B row stride, XOR swizzle
#define OFF_B    65536    // 131072: FULL B fp16 [256][256], 512B row stride, XOR swizzle
                          //   ps overlay (128 x 185 fp32 = 94720) during spline
#define OFF_SMIN 196608   // 33280: input/output tile fp32 [128][65]
#define SMEM_BYTES 229888

__device__ __align__(16) __half g_w[(size_t)WROWS * 256u];   // fp16 weight plane
__device__ float g_h[(size_t)BTOT * 256u];                   // residual-h scratch (fp32)

static __device__ __forceinline__ uint32_t smem_u32(const void* p) {
    uint32_t a;
    asm("{ .reg .u64 t; cvta.to.shared.u64 t, %1; cvt.u32.u64 %0, t; }" : "=r"(a) : "l"(p));
    return a;
}
static __device__ __forceinline__ void ldmx4(uint32_t* r, uint32_t a) {
    asm volatile("ldmatrix.sync.aligned.m8n8.x4.shared.b16 {%0,%1,%2,%3}, [%4];"
                 : "=r"(r[0]), "=r"(r[1]), "=r"(r[2]), "=r"(r[3]) : "r"(a));
}
static __device__ __forceinline__ void mma_f16(float* c, const uint32_t* a, const uint32_t* b) {
    asm volatile("mma.sync.aligned.m16n8k16.row.col.f32.f16.f16.f32 "
                 "{%0,%1,%2,%3}, {%4,%5,%6,%7}, {%8,%9}, {%0,%1,%2,%3};"
                 : "+f"(c[0]), "+f"(c[1]), "+f"(c[2]), "+f"(c[3])
                 : "r"(a[0]), "r"(a[1]), "r"(a[2]), "r"(a[3]), "r"(b[0]), "r"(b[1]));
}
static __device__ __forceinline__ uint32_t pack_h2(float x0, float x1) {
    __half2 h2 = __float22half2_rn(make_float2(x0, x1));
    return *(uint32_t*)&h2;
}

// ---------------- weight convert kernel (fp32 -> single fp16 plane) ----------------
// rows: 0-255 w_in | 256-511 w0a | 512-767 w1a | 768-1023 w0b | 1024-1279 w1b
//       1280-2015 w_out (tight) | 2016-2047 zero pad
__global__ void split_weights_kernel(
    const float* __restrict__ w_in, const float* __restrict__ w0a,
    const float* __restrict__ w1a,  const float* __restrict__ w0b,
    const float* __restrict__ w1b,  const float* __restrict__ w_out)
{
    int row = blockIdx.x;
    int c = threadIdx.x;
    float v = 0.f;
    if (row < 256)       { if (c < 32) v = w_in[row * 32 + c]; }
    else if (row < 512)  v = w0a[(row - 256) * 256 + c];
    else if (row < 768)  v = w1a[(row - 512) * 256 + c];
    else if (row < 1024) v = w0b[(row - 768) * 256 + c];
    else if (row < 1280) v = w1b[(row - 1024) * 256 + c];
    else if (row < 2016) v = w_out[(row - 1280) * 256 + c];
    g_w[(size_t)row * 256 + c] = __float2half(v);
}

// ---------------- one K=16 chunk, warp tile 32x64, N=256: 6 ldm + 16 mma / warp ----------------
static __device__ __forceinline__ void compute_chunk(
    uint32_t Aop, uint32_t Bop, float* acc, int wm, int wn, int k0, int lane)
{
    uint32_t ah[2][4];
    #pragma unroll
    for (int mt = 0; mt < 2; mt++) {
        int r = 32 * wm + 16 * mt + (lane & 15);
        int c = (k0 >> 3) + (lane >> 4);
        uint32_t ad = Aop + r * 512 + ((uint32_t)(c ^ (r & 7)) << 4);
        ldmx4(ah[mt], ad);
    }
    uint32_t bh[4][4];
    #pragma unroll
    for (int g = 0; g < 4; g++) {
        int r = 64 * wn + 16 * g + (lane & 15);
        int c = (k0 >> 3) + (lane >> 4);
        uint32_t bd = Bop + r * 512 + ((uint32_t)(c ^ (r & 7)) << 4);
        ldmx4(bh[g], bd);
    }
    #pragma unroll
    for (int mt = 0; mt < 2; mt++)
        #pragma unroll
        for (int nt = 0; nt < 8; nt++) {
            int g = nt >> 1, o = nt & 1;
            uint32_t b0[2] = { bh[g][o], bh[g][o + 2] };
            mma_f16(acc + (mt * 8 + nt) * 4, ah[mt], b0);
        }
}

// ---------------- same, N=192 (w_out): 5 ldm + 12 mma / warp (warp tile 32x48) ----------------
static __device__ __forceinline__ void compute_chunk192(
    uint32_t Aop, uint32_t Bop, float* acc, int wm, int wn, int k0, int lane)
{
    uint32_t ah[2][4];
    #pragma unroll
    for (int mt = 0; mt < 2; mt++) {
        int r = 32 * wm + 16 * mt + (lane & 15);
        int c = (k0 >> 3) + (lane >> 4);
        uint32_t ad = Aop + r * 512 + ((uint32_t)(c ^ (r & 7)) << 4);
        ldmx4(ah[mt], ad);
    }
    uint32_t bh[3][4];
    #pragma unroll
    for (int g = 0; g < 3; g++) {
        int r = 48 * wn + 16 * g + (lane & 15);
        int c = (k0 >> 3) + (lane >> 4);
        uint32_t bd = Bop + r * 512 + ((uint32_t)(c ^ (r & 7)) << 4);
        ldmx4(bh[g], bd);
    }
    #pragma unroll
    for (int mt = 0; mt < 2; mt++)
        #pragma unroll
        for (int nt = 0; nt < 6; nt++) {
            int g = nt >> 1, o = nt & 1;
            uint32_t b0[2] = { bh[g][o], bh[g][o + 2] };
            mma_f16(acc + (mt * 8 + nt) * 4, ah[mt], b0);
        }
}

// ---------------- full-B-resident GEMM: stage once, then barrier-free mainloop ----------------
template <int N256, int KCH>
static __device__ __forceinline__ void run_gemm(
    uint32_t smb, uint32_t Aop, int rowbase,
    float* acc, int wm, int wn, int lane, int tid)
{
    const int rows = N256 ? 256 : 192;
    #pragma unroll
    for (int q = 0; q < 64; q++) acc[q] = 0.f;
    const uint32_t Bop = smb + OFF_B;
    const int pieces = KCH * 2;            // 16B pieces per row
    const int total = rows * pieces;
    #pragma unroll 4
    for (int o = tid; o < total; o += NTH) {
        int row = o / pieces, p = o - row * pieces;
        const __half* src = g_w + (size_t)(rowbase + row) * 256 + p * 8;
        uint32_t dst = Bop + row * 512 + ((uint32_t)(p ^ (row & 7)) << 4);
        asm volatile("cp.async.cg.shared.global [%0], [%1], 16;" :: "r"(dst), "l"(src));
    }
    asm volatile("cp.async.commit_group;");
    asm volatile("cp.async.wait_group 0;");
    __syncthreads();
    #pragma unroll 2
    for (int t = 0; t < KCH; t++) {
        if (N256) compute_chunk(Aop, Bop, acc, wm, wn, 16 * t, lane);
        else      compute_chunk192(Aop, Bop, acc, wm, wn, 16 * t, lane);
    }
    __syncthreads();   // all reads of A/B done before epilogue overwrites A / ps overlays B
}

// epilogue. MODE 0: h=C+b (store h), relu->A | 1: relu(C+b)->A
// MODE 2: h=h_old+C+b (store h), relu->A | 3: h=h_old+C+b, raw->A (no h store)
template <int MODE>
static __device__ __forceinline__ void epi(
    char* sm, const float* acc, const float* __restrict__ bias,
    int row0, int wm, int wn, int lane)
{
    #pragma unroll
    for (int mt = 0; mt < 2; mt++)
        #pragma unroll
        for (int nt = 0; nt < 8; nt++) {
            const float* a = acc + (mt * 8 + nt) * 4;
            int c0 = 64 * wn + 8 * nt + 2 * (lane & 3);
            float bb0 = __ldg(bias + c0);
            float bb1 = __ldg(bias + c0 + 1);
            #pragma unroll
            for (int hf = 0; hf < 2; hf++) {
                int rl = 32 * wm + 16 * mt + (lane >> 2) + 8 * hf;
                float v0 = a[2 * hf] + bb0, v1 = a[2 * hf + 1] + bb1;
                float* hp = g_h + (size_t)(row0 + rl) * 256 + c0;
                if (MODE == 2 || MODE == 3) {
                    float2 ho = *(float2*)hp;
                    v0 += ho.x; v1 += ho.y;
                }
                if (MODE == 0 || MODE == 2) *(float2*)hp = make_float2(v0, v1);
                float w0 = v0, w1 = v1;
                if (MODE != 3) { w0 = fmaxf(w0, 0.f); w1 = fmaxf(w1, 0.f); }
                int u = 8 * wn + nt;
                uint32_t off = OFF_A + rl * 512
                             + ((uint32_t)(u ^ (rl & 7)) << 4) + 4 * (lane & 3);
                *(uint32_t*)(sm + off) = pack_h2(w0, w1);
            }
        }
}

// w_out epilogue: C -> ps fp32 [128][185] (overlaid on B region)
static __device__ __forceinline__ void epilogue_ps(
    char* sm, const float* acc, int wm, int wn, int lane)
{
    float* ps = (float*)(sm + OFF_B);
    #pragma unroll
    for (int mt = 0; mt < 2; mt++)
        #pragma unroll
        for (int nt = 0; nt < 6; nt++) {
            const float* a = acc + (mt * 8 + nt) * 4;
            int c0 = 48 * wn + 8 * nt + 2 * (lane & 3);
            #pragma unroll
            for (int hf = 0; hf < 2; hf++) {
                int r = 32 * wm + 16 * mt + (lane >> 2) + 8 * hf;
                if (c0 < 184)     ps[r * 185 + c0]     = a[2 * hf];
                if (c0 + 1 < 184) ps[r * 185 + c0 + 1] = a[2 * hf + 1];
            }
        }
}

// spline for 2 dims of one row (512 thr = 128 rows x 4 thr, 2 dims each)
static __device__ __forceinline__ void spline_block(
    char* sm, float* smin, const float* __restrict__ b_out,
    int p, int tid, float* lad)
{
    float* ps = (float*)(sm + OFF_B);
    int r = tid >> 2, s = tid & 3;
    #pragma unroll 1
    for (int dd = 0; dd < 2; dd++) {
        int dl = s + 4 * dd;
        int gd = 8 * p + dl;
        const float* qp = ps + r * 185 + dl * 23;
        float pp[23];
        #pragma unroll
        for (int j = 0; j < 23; j++) pp[j] = qp[j] + __ldg(b_out + gd * 23 + j);
        float knw[9], knh[9], dv[9];
        {
            float e[8], mx = -1e30f;
            #pragma unroll
            for (int j = 0; j < 8; j++) { e[j] = pp[j] * 0.0625f; mx = fmaxf(mx, e[j]); }
            float se = 0.f;
            #pragma unroll
            for (int j = 0; j < 8; j++) { e[j] = expf(e[j] - mx); se += e[j]; }
            float inv = 1.f / se, cum = 0.f;
            knw[0] = -3.f;
            #pragma unroll
            for (int j = 0; j < 8; j++) { cum += 0.001f + 0.992f * e[j] * inv; knw[j + 1] = 6.f * cum - 3.f; }
            knw[8] = 3.f;
        }
        {
            float e[8], mx = -1e30f;
            #pragma unroll
            for (int j = 0; j < 8; j++) { e[j] = pp[8 + j] * 0.0625f; mx = fmaxf(mx, e[j]); }
            float se = 0.f;
            #pragma unroll
            for (int j = 0; j < 8; j++) { e[j] = expf(e[j] - mx); se += e[j]; }
            float inv = 1.f / se, cum = 0.f;
            knh[0] = -3.f;
            #pragma unroll
            for (int j = 0; j < 8; j++) { cum += 0.001f + 0.992f * e[j] * inv; knh[j + 1] = 6.f * cum - 3.f; }
            knh[8] = 3.f;
        }
        dv[0] = 1.f; dv[8] = 1.f;
        #pragma unroll
        for (int j = 1; j < 8; j++) {
            float t = pp[15 + j];
            dv[j] = 0.001f + fmaxf(t, 0.f) + log1pf(expf(-fabsf(t)));
        }
        float x  = smin[r * 65 + 2 * gd];
        float xc = fminf(fmaxf(x, -3.f), 3.f);
        int idx = -1;
        #pragma unroll
        for (int j = 0; j < 9; j++) idx += (xc >= knw[j]) ? 1 : 0;
        idx = min(max(idx, 0), 7);
        float kw0 = knw[idx], kw1 = knw[idx + 1];
        float kh0 = knh[idx], kh1 = knh[idx + 1];
        float wdt = kw1 - kw0, hgt = kh1 - kh0;
        float delta = hgt / wdt;
        float d0v = dv[idx], d1v = dv[idx + 1];
        float th  = (xc - kw0) / wdt;
        float tom = th * (1.f - th);
        float num = hgt * (delta * th * th + d0v * tom);
        float den = delta + (d0v + d1v - 2.f * delta) * tom;
        float y   = kh0 + num / den;
        float omt = 1.f - th;
        float dnum = delta * delta * (d1v * th * th + 2.f * delta * tom + d0v * omt * omt);
        float ld   = logf(dnum) - 2.f * logf(den);
        bool inside = (x >= -3.f) && (x <= 3.f);
        if (!inside) { y = x; ld = 0.f; }
        smin[r * 65 + 2 * gd] = y;
        *lad += ld;
    }
}

__global__ void __launch_bounds__(NTH, 1)
coupling_mma_kernel(const float* __restrict__ inp,
                    const float* __restrict__ b_in,
                    const float* __restrict__ b0a, const float* __restrict__ b1a,
                    const float* __restrict__ b0b, const float* __restrict__ b1b,
                    const float* __restrict__ b_out,
                    float* __restrict__ out)
{
    extern __shared__ char sm[];
    const int tid = threadIdx.x, lane = tid & 31, wrp = tid >> 5;
    const int wm = wrp >> 2, wn = wrp & 3;        // 4 x 4 warp grid, 32x64 tiles
    const int row0 = blockIdx.x * MR;
    const uint32_t smb = smem_u32(sm);
    float* smin = (float*)(sm + OFF_SMIN);

    // ---- load input tile 128 x 64 (stride 65) ----
    #pragma unroll
    for (int i = 0; i < 16; i++) {
        int idx = tid + NTH * i;
        int r = idx >> 6, c = idx & 63;
        smin[r * 65 + c] = inp[(size_t)(row0 + r) * 64 + c];
    }
    __syncthreads();

    // ---- ident (odd cols) -> A as fp16, k = 0..31 (4 threads/row) ----
    {
        int r = tid >> 2, s = tid & 3;
        #pragma unroll
        for (int kk = 0; kk < 8; kk += 2) {
            int k = 8 * s + kk;
            float v0 = smin[r * 65 + 2 * k + 1];
            float v1 = smin[r * 65 + 2 * k + 3];
            int u = k >> 3;
            uint32_t off = OFF_A + r * 512
                         + ((uint32_t)(u ^ (r & 7)) << 4) + (k & 7) * 2;
            *(uint32_t*)(sm + off) = pack_h2(v0, v1);
        }
    }
    // visibility via the __syncthreads inside run_gemm before first compute

    float acc[64];
    const uint32_t Aop = smb + OFF_A;

    run_gemm<1, 2>(smb, Aop, 0, acc, wm, wn, lane, tid);     // w_in (K=32)
    epi<0>(sm, acc, b_in, row0, wm, wn, lane);
    run_gemm<1, 16>(smb, Aop, 256, acc, wm, wn, lane, tid);  // w0a
    epi<1>(sm, acc, b0a, row0, wm, wn, lane);
    run_gemm<1, 16>(smb, Aop, 512, acc, wm, wn, lane, tid);  // w1a
    epi<2>(sm, acc, b1a, row0, wm, wn, lane);
    run_gemm<1, 16>(smb, Aop, 768, acc, wm, wn, lane, tid);  // w0b
    epi<1>(sm, acc, b0b, row0, wm, wn, lane);
    run_gemm<1, 16>(smb, Aop, 1024, acc, wm, wn, lane, tid); // w1b -> raw h
    epi<3>(sm, acc, b1b, row0, wm, wn, lane);

    // ---- w_out: 4 passes x 184 tight cols (8 dims x 23), N=192 GEMM, full-tile spline ----
    float lad = 0.f;
    #pragma unroll 1
    for (int p = 0; p < 4; p++) {
        run_gemm<0, 16>(smb, Aop, 1280 + 184 * p, acc, wm, wn, lane, tid);
        epilogue_ps(sm, acc, wm, wn, lane);
        __syncthreads();
        spline_block(sm, smin, b_out, p, tid, &lad);
        __syncthreads();    // ps consumed before next pass stages into B region
    }

    lad += __shfl_xor_sync(0xffffffffu, lad, 1);
    lad += __shfl_xor_sync(0xffffffffu, lad, 2);

    __syncthreads();
    #pragma unroll
    for (int i = 0; i < 16; i++) {
        int idx = tid + NTH * i;
        int r = idx >> 6, c = idx & 63;
        out[(size_t)(row0 + r) * 64 + c] = smin[r * 65 + c];
    }
    if ((tid & 3) == 0) out[(size_t)BTOT * 64 + row0 + (tid >> 2)] = lad;
}

extern "C" void kernel_launch(void* const* d_in, const int* in_sizes, int n_in,
                              void* d_out, int out_size)
{
    cudaFuncSetAttribute(coupling_mma_kernel,
                         cudaFuncAttributeMaxDynamicSharedMemorySize, SMEM_BYTES);
    const float* inp   = (const float*)d_in[0];
    const float* w_in  = (const float*)d_in[1];
    const float* b_in  = (const float*)d_in[2];
    const float* w0a   = (const float*)d_in[3];
    const float* b0a   = (const float*)d_in[4];
    const float* w1a   = (const float*)d_in[5];
    const float* b1a   = (const float*)d_in[6];
    const float* w0b   = (const float*)d_in[7];
    const float* b0b   = (const float*)d_in[8];
    const float* w1b   = (const float*)d_in[9];
    const float* b1b   = (const float*)d_in[10];
    const float* w_out = (const float*)d_in[11];
    const float* b_out = (const float*)d_in[12];
    float* out = (float*)d_out;

    split_weights_kernel<<<WROWS, 256>>>(w_in, w0a, w1a, w0b, w1b, w_out);
    coupling_mma_kernel<<<GRID, NTH, SMEM_BYTES>>>(
        inp, b_in, b0a, b1a, b0b, b1b, b_out, out);
}